// round 3
// baseline (speedup 1.0000x reference)
#include <cuda_runtime.h>
#include <cuda_bf16.h>

// B = 2,000,000 rows, M=3, L=16.
// inputs: d_in[0]=x (B*3 f32), d_in[1]=phis (48), d_in[2]=interval (3),
//         d_in[3]=weight (48). out = concat(y[B], weight[48]).
//
// Per coordinate m, the 16-bit cond mask is piecewise-constant in x_m over 33
// intervals delimited by the exact float thresholds of fl(x-phi) <= +-iv.
// Winner masks: w2 = m2; w1 = m1 & ~(m2<<3); w0 = m0 & ~(m1<<3) & ~(m2<<6).
// Split the resolved weighted sums by dependency rank:
//   S2(k2)        = sum over w2 bits of (A,B,C)   -> 33 entries  (smem)
//   S1(k1,k2)     = sum over w1 bits              -> 1089 entries (smem)
//   T0(k0,k1,k2)  = sum over w0 bits              -> 33^3 entries (L2, 16B/row)
// Row eval: 3 branchless binary searches + 1 LDG + 2 LDS + 3 sincos + 9 FMA.

#define NK  33
#define NK2 (NK * NK)          // 1089
#define NT0 (NK * NK * NK)     // 35937

__device__ float4 g_T0[NT0];   // (A0,B0,C0,0)
__device__ float4 g_S1[NK2];   // (A1,B1,C1,0)
__device__ float4 g_S2[NK];    // (A2,B2,C2,0)
__device__ float  g_bp[3][32]; // sorted breakpoints per m

#define F_INF  __int_as_float(0x7f800000)
#define F_NINF __int_as_float(0xff800000)

// Setup + table fill. Every block redundantly computes thresholds/masks/abc in
// smem (cheap: ULP-walk), then fills its slice of T0. Block 0 also writes
// S1, S2, g_bp, and the weight passthrough.
__global__ void table_kernel(const float* __restrict__ phis,
                             const float* __restrict__ interval,
                             const float* __restrict__ weight,
                             float* __restrict__ out_w, int copy_w)
{
    __shared__ float    s_tlo[3][16], s_thi[3][16];
    __shared__ float    s_th[3][32], s_bp[3][32];
    __shared__ unsigned s_cm[3][NK];
    __shared__ float4   s_abc[48];
    int t = threadIdx.x;

    // Exact flip thresholds t = max{x : fl(x - phi) <= c} via ULP-walk.
    // fl(x-phi) is monotone in x, and fl(phi+c) is within ~1 ULP of the flip.
    if (t < 96) {
        int m = t / 32, j = t % 32, l = j >> 1, hi = j & 1;
        float phi = phis[m * 16 + l];
        float iv  = interval[m];
        float c   = hi ? iv : -iv;
        float tt  = phi + c;
        if (tt - phi <= c) {
            #pragma unroll 1
            for (int it = 0; it < 64; ++it) {
                float n = nextafterf(tt, F_INF);
                if (n - phi <= c) tt = n; else break;
            }
        } else {
            #pragma unroll 1
            for (int it = 0; it < 64; ++it) {
                tt = nextafterf(tt, F_NINF);
                if (tt - phi <= c) break;
            }
        }
        s_th[m][j] = tt;
        if (hi) s_thi[m][l] = tt; else s_tlo[m][l] = tt;
    }
    if (t < 48) {
        int m = t >> 4, l = t & 15;
        float w = weight[m * 3 + l];     // segment id s = 3m + l
        float sp, cp;
        sincosf(phis[t], &sp, &cp);
        s_abc[t] = make_float4(0.5f * cp * w, 0.5f * sp * w, 0.5f * w, 0.0f);
        if (copy_w && blockIdx.x == 0) out_w[t] = weight[t];
    }
    __syncthreads();

    // Rank sort (32 per m, ties by index).
    if (t < 96) {
        int m = t / 32, j = t % 32;
        float v = s_th[m][j];
        int r = 0;
        for (int q = 0; q < 32; q++) {
            float u = s_th[m][q];
            r += (u < v) || (u == v && q < j);
        }
        s_bp[m][r] = v;
    }
    __syncthreads();

    // Cond mask per interval k = (bp[k-1], bp[k]]; representative x = bp[k].
    if (t < 99) {
        int m = t / 33, k = t % 33;
        unsigned mask = 0;
        if (k < 32) {
            float xv = s_bp[m][k];
            #pragma unroll
            for (int l = 0; l < 16; l++)
                if (xv > s_tlo[m][l] && xv <= s_thi[m][l]) mask |= (1u << l);
        }
        s_cm[m][k] = mask;
    }
    __syncthreads();

    // Fill T0 slice: (A0,B0,C0) for winner bits of m=0.
    int idx = blockIdx.x * blockDim.x + t;
    if (idx < NT0) {
        int k0 = idx / NK2;
        int r  = idx % NK2;
        int k1 = r / NK, k2 = r % NK;
        unsigned w0 = s_cm[0][k0] & ~(s_cm[1][k1] << 3) & ~(s_cm[2][k2] << 6);
        float A = 0, Bv = 0, C = 0;
        #pragma unroll
        for (int l = 0; l < 16; l++)
            if ((w0 >> l) & 1u) { float4 q = s_abc[l]; A += q.x; Bv += q.y; C += q.z; }
        g_T0[idx] = make_float4(A, Bv, C, 0.0f);
    }

    if (blockIdx.x == 0) {
        for (int i = t; i < NK2; i += blockDim.x) {
            int k1 = i / NK, k2 = i % NK;
            unsigned w1 = s_cm[1][k1] & ~(s_cm[2][k2] << 3);
            float A = 0, Bv = 0, C = 0;
            #pragma unroll
            for (int l = 0; l < 16; l++)
                if ((w1 >> l) & 1u) { float4 q = s_abc[16 + l]; A += q.x; Bv += q.y; C += q.z; }
            g_S1[i] = make_float4(A, Bv, C, 0.0f);
        }
        if (t < NK) {
            unsigned w2 = s_cm[2][t];
            float A = 0, Bv = 0, C = 0;
            #pragma unroll
            for (int l = 0; l < 16; l++)
                if ((w2 >> l) & 1u) { float4 q = s_abc[32 + l]; A += q.x; Bv += q.y; C += q.z; }
            g_S2[t] = make_float4(A, Bv, C, 0.0f);
        }
        if (t < 96) g_bp[t / 32][t % 32] = s_bp[t / 32][t % 32];
    }
}

__device__ __forceinline__ int bsearch32(const float* __restrict__ b, float x)
{
    int it = 0;
    if (b[15]     < x) it  = 16;
    if (b[it + 7] < x) it += 8;
    if (b[it + 3] < x) it += 4;
    if (b[it + 1] < x) it += 2;
    if (b[it]     < x) it += 1;
    if (b[it]     < x) it += 1;   // count == 32 case
    return it;
}

// Main: 8 rows/thread via 6 float4 loads / 2 float4 stores.
__global__ __launch_bounds__(256)
void bspline_kernel(const float4* __restrict__ x4, float4* __restrict__ y4, int n8)
{
    __shared__ float  sbp[3][32];
    __shared__ float4 sS1[NK2];
    __shared__ float4 sS2[NK];
    int t = threadIdx.x;
    if (t < 96) sbp[t / 32][t % 32] = g_bp[t / 32][t % 32];
    for (int i = t; i < NK2; i += 256) sS1[i] = g_S1[i];
    if (t < NK) sS2[t] = g_S2[t];
    __syncthreads();

    int g = blockIdx.x * 256 + t;
    if (g >= n8) return;

    float4 v[6];
    #pragma unroll
    for (int i = 0; i < 6; i++) v[i] = x4[6 * g + i];
    const float* f = (const float*)v;   // 24 floats = 8 rows x 3 coords

    float res[8];
    #pragma unroll
    for (int e = 0; e < 8; e++) {
        float xa = f[3 * e], xb = f[3 * e + 1], xc = f[3 * e + 2];
        int k0 = bsearch32(sbp[0], xa);
        int k1 = bsearch32(sbp[1], xb);
        int k2 = bsearch32(sbp[2], xc);
        float4 t0 = __ldg(&g_T0[(k0 * NK + k1) * NK + k2]);
        float4 s1 = sS1[k1 * NK + k2];
        float4 s2 = sS2[k2];
        float sa, ca, sb, cb, sc, cc;
        __sincosf(xa, &sa, &ca);
        __sincosf(xb, &sb, &cb);
        __sincosf(xc, &sc, &cc);
        float r = t0.z + s1.z + s2.z;
        r = fmaf(ca, t0.x, r); r = fmaf(sa, t0.y, r);
        r = fmaf(cb, s1.x, r); r = fmaf(sb, s1.y, r);
        r = fmaf(cc, s2.x, r); r = fmaf(sc, s2.y, r);
        res[e] = r;
    }
    float4* ro = (float4*)res;
    y4[2 * g]     = ro[0];
    y4[2 * g + 1] = ro[1];
}

// Scalar tail for B % 8 != 0 (unused for B = 2e6).
__global__ void tail_kernel(const float* __restrict__ x, float* __restrict__ y,
                            int start, int B)
{
    int i = start + blockIdx.x * blockDim.x + threadIdx.x;
    if (i >= B) return;
    float xa = x[3 * i], xb = x[3 * i + 1], xc = x[3 * i + 2];
    int k0 = bsearch32(g_bp[0], xa);
    int k1 = bsearch32(g_bp[1], xb);
    int k2 = bsearch32(g_bp[2], xc);
    float4 t0 = g_T0[(k0 * NK + k1) * NK + k2];
    float4 s1 = g_S1[k1 * NK + k2];
    float4 s2 = g_S2[k2];
    float sa, ca, sb, cb, sc, cc;
    __sincosf(xa, &sa, &ca);
    __sincosf(xb, &sb, &cb);
    __sincosf(xc, &sc, &cc);
    float r = t0.z + s1.z + s2.z;
    r = fmaf(ca, t0.x, r); r = fmaf(sa, t0.y, r);
    r = fmaf(cb, s1.x, r); r = fmaf(sb, s1.y, r);
    r = fmaf(cc, s2.x, r); r = fmaf(sc, s2.y, r);
    y[i] = r;
}

extern "C" void kernel_launch(void* const* d_in, const int* in_sizes, int n_in,
                              void* d_out, int out_size)
{
    const float* x        = (const float*)d_in[0];
    const float* phis     = (const float*)d_in[1];
    const float* interval = (const float*)d_in[2];
    const float* weight   = (const float*)d_in[3];
    float* out = (float*)d_out;

    int B = in_sizes[0] / 3;
    int copy_w = (out_size >= B + 48) ? 1 : 0;

    table_kernel<<<(NT0 + 255) / 256, 256>>>(phis, interval, weight, out + B, copy_w);

    int n8 = B >> 3;
    if (n8 > 0) {
        int blocks = (n8 + 255) / 256;
        bspline_kernel<<<blocks, 256>>>((const float4*)x, (float4*)out, n8);
    }
    int rem = B - (n8 << 3);
    if (rem > 0) {
        tail_kernel<<<1, 256>>>(x, out, n8 << 3, B);
    }
}